// round 4
// baseline (speedup 1.0000x reference)
#include <cuda_runtime.h>
#include <math.h>

#define Bn 128
#define Cn 48
#define Hn 64
#define Wn 64
#define Pn 32
#define OUT_ELEMS (Bn*Cn*Hn*Wn)

// Scratch (no allocations allowed)
__device__ float  g_M[Cn*Cn];     // combined bilinear matrix (includes 1/scale)
__device__ float4 g_Spart[512];   // score partials: idx = (b*2+g)*2 + khalf

#define FMA2(acc, mm, vv) asm("fma.rn.f32x2 %0, %1, %2, %0;" : "+l"(acc) : "l"(mm), "l"(vv))
#define PACK2(dst, lo, hi) asm("mov.b64 %0, {%1,%2};" : "=l"(dst) : "f"(lo), "f"(hi))
#define UNPACK2(lo, hi, src) asm("mov.b64 {%0,%1}, %2;" : "=f"(lo), "=f"(hi) : "l"(src))

// ---------------------------------------------------------------------------
// Kernel A: warp-per-output. M[c][c2] = sum_o (Wq1[o,c]Wk1[o,c2]+...)/scale.
// ---------------------------------------------------------------------------
__global__ __launch_bounds__(256) void prep_kernel(
        const float* __restrict__ Wq1, const float* __restrict__ Wq2,
        const float* __restrict__ Wq3, const float* __restrict__ Wk1,
        const float* __restrict__ Wk2, const float* __restrict__ Wk3) {
    int w    = (blockIdx.x * 256 + threadIdx.x) >> 5;
    int lane = threadIdx.x & 31;
    if (w >= Cn*Cn) return;
    int c = w / Cn, c2 = w % Cn;

    float s = 0.f;
    #pragma unroll
    for (int o = lane; o < Cn; o += 32) {
        s += Wq1[o*Cn+c]*Wk1[o*Cn+c2]
           + Wq2[o*Cn+c]*Wk2[o*Cn+c2]
           + Wq3[o*Cn+c]*Wk3[o*Cn+c2];
    }
    #pragma unroll
    for (int off = 16; off; off >>= 1)
        s += __shfl_xor_sync(0xffffffffu, s, off);

    if (lane == 0) g_M[w] = s * (1.0f / sqrtf((float)(Cn*Pn*Pn)));
}

// ---------------------------------------------------------------------------
// Kernel B: Gram-based scores. Grid 512: bid -> (b, g, khalf).
// Y = [vt(48ch); vb(48ch)] over 512 masked pixels of (b,g); this block handles
// 128 pixel-pairs (khalf). 136 of 160 threads tile the lower triangle of the
// 96x96 Gram G = Y Y^T with 6x6 tiles; FMA2 packs the 2 pixels of a float4.
// Epilogue contracts G-tiles with M to the 4 score partials.
// ---------------------------------------------------------------------------
__global__ __launch_bounds__(160) void score_kernel(const float* __restrict__ x) {
    __shared__ unsigned long long sY[96*17];   // [r][pair k], stride 17 (13056 B)
    __shared__ float sM[Cn*Cn];                // 9216 B
    __shared__ float4 sred[5];

    const int bid = blockIdx.x;
    const int h = bid & 1;             // k-half
    const int g = (bid >> 1) & 1;      // column-block / parity group
    const int b = bid >> 2;
    const int tid = threadIdx.x;

    // load M (epilogue only)
    for (int i = tid; i < Cn*Cn; i += 160) sM[i] = g_M[i];

    // tile coords from lower-triangle enumeration t = i(i+1)/2 + j
    int ti = 0, tj = 0;
    const bool active = (tid < 136);
    if (active) {
        int t = tid;
        ti = (int)floorf((sqrtf(8.0f*t + 1.0f) - 1.0f) * 0.5f);
        while ((ti+1)*(ti+2)/2 <= t) ++ti;
        while (ti*(ti+1)/2 > t) --ti;
        tj = t - ti*(ti+1)/2;
    }

    const float4* xb4 = (const float4*)(x + (size_t)b * Cn * Hn * Wn);

    unsigned long long acc[36];
    #pragma unroll
    for (int i = 0; i < 36; ++i) acc[i] = 0ULL;

    // 8 stages; each stages 2 y-rows x 8 col-pairs = 16 pixel-pairs
    for (int s = 0; s < 8; ++s) {
        __syncthreads();
        // stage loads: 1536 float4 = 96 r x (2 yy x 8 q)
        for (int idx = tid; idx < 1536; idx += 160) {
            int q  = idx & 7;
            int yy = (idx >> 3) & 1;
            int r  = idx >> 4;
            int side = (r >= 48);
            int c    = r - side*48;
            int yg   = side*32 + h*16 + s*2 + yy;
            float4 v = xb4[((size_t)c*Hn + yg)*16 + g*8 + q];
            unsigned long long pk;
            if (g == 0) PACK2(pk, v.x, v.z);
            else        PACK2(pk, v.y, v.w);
            sY[r*17 + yy*8 + q] = pk;
        }
        __syncthreads();

        if (active) {
            #pragma unroll
            for (int k = 0; k < 16; ++k) {
                unsigned long long a2[6], b2[6];
                #pragma unroll
                for (int u = 0; u < 6; ++u) a2[u] = sY[(ti*6+u)*17 + k];
                #pragma unroll
                for (int w = 0; w < 6; ++w) b2[w] = sY[(tj*6+w)*17 + k];
                #pragma unroll
                for (int u = 0; u < 6; ++u)
                    #pragma unroll
                    for (int w = 0; w < 6; ++w)
                        FMA2(acc[u*6+w], a2[u], b2[w]);
            }
        }
    }
    __syncthreads();

    // epilogue: contract tile with M
    float p00 = 0.f, p01 = 0.f, p10 = 0.f, p11 = 0.f;
    if (active) {
        float sA = 0.f, sB = 0.f;
        #pragma unroll
        for (int u = 0; u < 6; ++u) {
            int r  = ti*6 + u;
            int cr = (r >= 48) ? (r - 48) : r;
            #pragma unroll
            for (int w = 0; w < 6; ++w) {
                int scol = tj*6 + w;
                int cs = (scol >= 48) ? (scol - 48) : scol;
                float lo, hi;
                UNPACK2(lo, hi, acc[u*6+w]);
                float gg = lo + hi;
                sA = fmaf(sM[cr*Cn + cs], gg, sA);
                sB = fmaf(sM[cs*Cn + cr], gg, sB);
            }
        }
        if (ti == tj) {                 // diagonal tile: each ordered pair once
            if (ti < 8) p00 = sA; else p11 = sA;
        } else if (ti < 8) {            // tt off-diagonal (ti > tj, both < 8)
            p00 = sA + sB;
        } else if (tj >= 8) {           // bb off-diagonal
            p11 = sA + sB;
        } else {                        // cross quadrant: G_bt entries
            p10 = sA;  p01 = sB;
        }
    }

    #pragma unroll
    for (int off = 16; off; off >>= 1) {
        p00 += __shfl_xor_sync(0xffffffffu, p00, off);
        p01 += __shfl_xor_sync(0xffffffffu, p01, off);
        p10 += __shfl_xor_sync(0xffffffffu, p10, off);
        p11 += __shfl_xor_sync(0xffffffffu, p11, off);
    }
    int wid = tid >> 5;
    if ((tid & 31) == 0) sred[wid] = make_float4(p00, p01, p10, p11);
    __syncthreads();
    if (tid == 0) {
        float4 sv = sred[0];
        #pragma unroll
        for (int w = 1; w < 5; ++w) {
            float4 t = sred[w];
            sv.x += t.x; sv.y += t.y; sv.z += t.z; sv.w += t.w;
        }
        g_Spart[(b*2+g)*2 + h] = sv;
    }
}

// ---------------------------------------------------------------------------
// Kernel C: output assembly with fused attn (softmax coeffs + logdet).
// ---------------------------------------------------------------------------
__global__ __launch_bounds__(256) void out_kernel(const float* __restrict__ x,
                                                  const float* __restrict__ logdet_in,
                                                  const float* __restrict__ off1p,
                                                  const float* __restrict__ off2p,
                                                  const float* __restrict__ off3p,
                                                  float* __restrict__ out, int out_size) {
    __shared__ float sc[2][4];
    __shared__ float sld[2];

    int tid = threadIdx.x;
    int blk = blockIdx.x;
    int r = blk >> 1;              // r = b*48 + c (constant per block)
    int b = r / Cn;
    int c = r % Cn;

    // issue main loads first (independent of the coeffs)
    int t  = blk * 256 + tid;
    int x4 = t & 15;
    int y  = (t >> 4) & 31;
    int g  = x4 >> 3;
    size_t base = (((size_t)b*Cn + c)*Hn + y)*Wn + x4*4;
    float4 xt = *(const float4*)(x + base);
    float4 xb = *(const float4*)(x + base + 32*Wn);

    if (tid < 2) {
        int gg = tid;
        const float off  = off1p[0];
        const float off2 = off2p[0];
        const float off3 = off3p[0];
        float4 s = g_Spart[(b*2+gg)*2 + 0];
        float4 tt2 = g_Spart[(b*2+gg)*2 + 1];
        s.x += tt2.x; s.y += tt2.y; s.z += tt2.z; s.w += tt2.w;

        float stt = s.x + off3, stb = s.y + off3;
        float sbt = s.z + off3, sbb = s.w + off3;
        float z = off3;

        float mx  = fmaxf(fmaxf(stt, stb), z);
        float e0  = expf(stt-mx), e1 = expf(stb-mx), ez = expf(z-mx);
        float inv = 1.f / (e0 + e1 + 2.f*ez);
        float a_tt = e0*inv + off2 + off;
        float a_tb = e1*inv + off2;

        mx  = fmaxf(fmaxf(sbt, sbb), z);
        e0  = expf(sbt-mx); e1 = expf(sbb-mx); ez = expf(z-mx);
        inv = 1.f / (e0 + e1 + 2.f*ez);
        float a_bt = e0*inv + off2;
        float a_bb = e1*inv + off2 + off;

        sc[gg][0]=a_tt; sc[gg][1]=a_tb; sc[gg][2]=a_bt; sc[gg][3]=a_bb;
        float det = a_tt*a_bb - a_tb*a_bt;
        sld[gg] = logf(fabsf(det)) * (float)(Pn*(Pn/2)*Cn);
    }
    __syncthreads();

    if (c == 0 && (blk & 1) == 0 && tid == 0) {
        if (OUT_ELEMS + b < out_size)
            out[OUT_ELEMS + b] = logdet_in[b] + sld[0] + sld[1];
    }

    float a_tt = sc[g][0], a_tb = sc[g][1], a_bt = sc[g][2], a_bb = sc[g][3];

    float4 ot, ob;
    if (g == 0) {  // pass-through at even lane (x,z)
        ot.x = xt.x;                    ob.x = xb.x;
        ot.y = a_tt*xt.y + a_tb*xb.y;   ob.y = a_bt*xt.y + a_bb*xb.y;
        ot.z = xt.z;                    ob.z = xb.z;
        ot.w = a_tt*xt.w + a_tb*xb.w;   ob.w = a_bt*xt.w + a_bb*xb.w;
    } else {       // pass-through at odd lane (y,w)
        ot.x = a_tt*xt.x + a_tb*xb.x;   ob.x = a_bt*xt.x + a_bb*xb.x;
        ot.y = xt.y;                    ob.y = xb.y;
        ot.z = a_tt*xt.z + a_tb*xb.z;   ob.z = a_bt*xt.z + a_bb*xb.z;
        ot.w = xt.w;                    ob.w = xb.w;
    }
    __stcs((float4*)(out + base), ot);
    __stcs((float4*)(out + base + 32*Wn), ob);
}

// ---------------------------------------------------------------------------
extern "C" void kernel_launch(void* const* d_in, const int* in_sizes, int n_in,
                              void* d_out, int out_size) {
    const float* x      = (const float*)d_in[0];
    const float* logdet = (const float*)d_in[1];
    const float* Wq1    = (const float*)d_in[2];
    const float* Wq2    = (const float*)d_in[3];
    const float* Wq3    = (const float*)d_in[4];
    const float* Wk1    = (const float*)d_in[5];
    const float* Wk2    = (const float*)d_in[6];
    const float* Wk3    = (const float*)d_in[7];
    const float* off1   = (const float*)d_in[8];
    const float* off2   = (const float*)d_in[9];
    const float* off3   = (const float*)d_in[10];
    float* out = (float*)d_out;

    prep_kernel<<<288, 256>>>(Wq1, Wq2, Wq3, Wk1, Wk2, Wk3);
    score_kernel<<<512, 160>>>(x);
    out_kernel<<<12288, 256>>>(x, logdet, off1, off2, off3, out, out_size);
}

// round 5
// speedup vs baseline: 1.1666x; 1.1666x over previous
#include <cuda_runtime.h>
#include <math.h>

#define Bn 128
#define Cn 48
#define Hn 64
#define Wn 64
#define Pn 32
#define OUT_ELEMS (Bn*Cn*Hn*Wn)

// Scratch (no allocations allowed)
__device__ unsigned long long g_M2[Cn*Cn];   // M duplicated (m,m) as f32x2
__device__ float4 g_Spart[2048];             // partials: idx = ((b*2+g)*8 + q)

#define FMA2(acc, mm, vv) asm("fma.rn.f32x2 %0, %1, %2, %0;" : "+l"(acc) : "l"(mm), "l"(vv))
#define PACK2(dst, lo, hi) asm("mov.b64 %0, {%1,%2};" : "=l"(dst) : "f"(lo), "f"(hi))
#define UNPACK2(lo, hi, src) asm("mov.b64 {%0,%1}, %2;" : "=f"(lo), "=f"(hi) : "l"(src))

// ---------------------------------------------------------------------------
// Kernel A: warp-per-output. M[c][c2] = sum_o (Wq1[o,c]Wk1[o,c2]+...)/scale.
// ---------------------------------------------------------------------------
__global__ __launch_bounds__(256) void prep_kernel(
        const float* __restrict__ Wq1, const float* __restrict__ Wq2,
        const float* __restrict__ Wq3, const float* __restrict__ Wk1,
        const float* __restrict__ Wk2, const float* __restrict__ Wk3) {
    int w    = (blockIdx.x * 256 + threadIdx.x) >> 5;
    int lane = threadIdx.x & 31;
    if (w >= Cn*Cn) return;
    int c = w / Cn, c2 = w % Cn;

    float s = 0.f;
    #pragma unroll
    for (int o = lane; o < Cn; o += 32) {
        s += Wq1[o*Cn+c]*Wk1[o*Cn+c2]
           + Wq2[o*Cn+c]*Wk2[o*Cn+c2]
           + Wq3[o*Cn+c]*Wk3[o*Cn+c2];
    }
    #pragma unroll
    for (int off = 16; off; off >>= 1)
        s += __shfl_xor_sync(0xffffffffu, s, off);

    if (lane == 0) {
        s *= (1.0f / sqrtf((float)(Cn*Pn*Pn)));
        ((float2*)g_M2)[w] = make_float2(s, s);
    }
}

// ---------------------------------------------------------------------------
// Kernel B: scores. Grid 2048: bid -> (b, g, y-quarter q). Block 256 threads.
// Stage V[48][64] packed (vt,vb) pixel-pairs in smem (4 y-rows x 16 cols of
// parity g). Warp ci computes rows ci*6..ci*6+5 of W = M V (broadcast M,
// stride-1 V, 12 indep FMA2 accumulators), then dots v.w -> 4 partials.
// ---------------------------------------------------------------------------
__global__ __launch_bounds__(256) void score_kernel(const float* __restrict__ x) {
    __shared__ unsigned long long sV[Cn*64];    // 24576 B  [c][k]
    __shared__ unsigned long long sM2[Cn*Cn];   // 18432 B
    __shared__ float4 sred[8];

    const int bid = blockIdx.x;
    const int q = bid & 7;             // y quarter (4 rows)
    const int g = (bid >> 3) & 1;      // column-parity group
    const int b = bid >> 4;
    const int tid = threadIdx.x;

    for (int i = tid; i < Cn*Cn; i += 256) sM2[i] = g_M2[i];

    const float2* xb2 = (const float2*)(x + (size_t)b * Cn * Hn * Wn);

    // stage V: 3072 entries / 256 threads = 12 iters, coalesced float2 loads
    for (int idx = tid; idx < Cn*64; idx += 256) {
        int c2 = idx >> 6;
        int k  = idx & 63;
        int yy = k >> 4;
        int xx = k & 15;
        int yt = q*4 + yy;
        float2 a  = xb2[((size_t)c2*Hn + yt)*32      + g*16 + xx];
        float2 bb = xb2[((size_t)c2*Hn + yt + 32)*32 + g*16 + xx];
        unsigned long long pk;
        if (g == 0) PACK2(pk, a.x, bb.x);
        else        PACK2(pk, a.y, bb.y);
        sV[idx] = pk;
    }
    __syncthreads();

    const int ci = tid >> 5;           // warp id: M-row group
    const int kl = tid & 31;           // k lane

    unsigned long long acc[12];
    #pragma unroll
    for (int i = 0; i < 12; ++i) acc[i] = 0ULL;

    #pragma unroll
    for (int c2 = 0; c2 < Cn; ++c2) {
        unsigned long long v0 = sV[c2*64 + kl];
        unsigned long long v1 = sV[c2*64 + kl + 32];
        #pragma unroll
        for (int r = 0; r < 6; ++r) {
            unsigned long long m = sM2[(ci*6 + r)*Cn + c2];   // broadcast
            FMA2(acc[r*2    ], m, v0);
            FMA2(acc[r*2 + 1], m, v1);
        }
    }

    // epilogue: p = v . w dots
    float p00 = 0.f, p01 = 0.f, p10 = 0.f, p11 = 0.f;
    #pragma unroll
    for (int r = 0; r < 6; ++r) {
        #pragma unroll
        for (int kk = 0; kk < 2; ++kk) {
            float wt, wb, vt, vb;
            UNPACK2(wt, wb, acc[r*2 + kk]);
            unsigned long long v = sV[(ci*6 + r)*64 + kl + kk*32];
            UNPACK2(vt, vb, v);
            p00 = fmaf(vt, wt, p00);  p01 = fmaf(vt, wb, p01);
            p10 = fmaf(vb, wt, p10);  p11 = fmaf(vb, wb, p11);
        }
    }

    #pragma unroll
    for (int off = 16; off; off >>= 1) {
        p00 += __shfl_xor_sync(0xffffffffu, p00, off);
        p01 += __shfl_xor_sync(0xffffffffu, p01, off);
        p10 += __shfl_xor_sync(0xffffffffu, p10, off);
        p11 += __shfl_xor_sync(0xffffffffu, p11, off);
    }
    if (kl == 0) sred[ci] = make_float4(p00, p01, p10, p11);
    __syncthreads();
    if (tid == 0) {
        float4 sv = sred[0];
        #pragma unroll
        for (int w = 1; w < 8; ++w) {
            float4 t = sred[w];
            sv.x += t.x; sv.y += t.y; sv.z += t.z; sv.w += t.w;
        }
        g_Spart[bid] = sv;
    }
}

// ---------------------------------------------------------------------------
// Kernel C: output assembly with fused attn (softmax coeffs + logdet).
// ---------------------------------------------------------------------------
__global__ __launch_bounds__(256) void out_kernel(const float* __restrict__ x,
                                                  const float* __restrict__ logdet_in,
                                                  const float* __restrict__ off1p,
                                                  const float* __restrict__ off2p,
                                                  const float* __restrict__ off3p,
                                                  float* __restrict__ out, int out_size) {
    __shared__ float sc[2][4];
    __shared__ float sld[2];

    int tid = threadIdx.x;
    int blk = blockIdx.x;
    int r = blk >> 1;              // r = b*48 + c (constant per block)
    int b = r / Cn;
    int c = r % Cn;

    // issue main loads first (independent of the coeffs)
    int t  = blk * 256 + tid;
    int x4 = t & 15;
    int y  = (t >> 4) & 31;
    int g  = x4 >> 3;
    size_t base = (((size_t)b*Cn + c)*Hn + y)*Wn + x4*4;
    float4 xt = *(const float4*)(x + base);
    float4 xb = *(const float4*)(x + base + 32*Wn);

    if (tid < 2) {
        int gg = tid;
        const float off  = off1p[0];
        const float off2 = off2p[0];
        const float off3 = off3p[0];
        float4 s = g_Spart[(b*2+gg)*8 + 0];
        #pragma unroll
        for (int qq = 1; qq < 8; ++qq) {
            float4 tt = g_Spart[(b*2+gg)*8 + qq];
            s.x += tt.x; s.y += tt.y; s.z += tt.z; s.w += tt.w;
        }
        float stt = s.x + off3, stb = s.y + off3;
        float sbt = s.z + off3, sbb = s.w + off3;
        float z = off3;

        float mx  = fmaxf(fmaxf(stt, stb), z);
        float e0  = expf(stt-mx), e1 = expf(stb-mx), ez = expf(z-mx);
        float inv = 1.f / (e0 + e1 + 2.f*ez);
        float a_tt = e0*inv + off2 + off;
        float a_tb = e1*inv + off2;

        mx  = fmaxf(fmaxf(sbt, sbb), z);
        e0  = expf(sbt-mx); e1 = expf(sbb-mx); ez = expf(z-mx);
        inv = 1.f / (e0 + e1 + 2.f*ez);
        float a_bt = e0*inv + off2;
        float a_bb = e1*inv + off2 + off;

        sc[gg][0]=a_tt; sc[gg][1]=a_tb; sc[gg][2]=a_bt; sc[gg][3]=a_bb;
        float det = a_tt*a_bb - a_tb*a_bt;
        sld[gg] = logf(fabsf(det)) * (float)(Pn*(Pn/2)*Cn);
    }
    __syncthreads();

    if (c == 0 && (blk & 1) == 0 && tid == 0) {
        if (OUT_ELEMS + b < out_size)
            out[OUT_ELEMS + b] = logdet_in[b] + sld[0] + sld[1];
    }

    float a_tt = sc[g][0], a_tb = sc[g][1], a_bt = sc[g][2], a_bb = sc[g][3];

    float4 ot, ob;
    if (g == 0) {  // pass-through at even lane (x,z)
        ot.x = xt.x;                    ob.x = xb.x;
        ot.y = a_tt*xt.y + a_tb*xb.y;   ob.y = a_bt*xt.y + a_bb*xb.y;
        ot.z = xt.z;                    ob.z = xb.z;
        ot.w = a_tt*xt.w + a_tb*xb.w;   ob.w = a_bt*xt.w + a_bb*xb.w;
    } else {       // pass-through at odd lane (y,w)
        ot.x = a_tt*xt.x + a_tb*xb.x;   ob.x = a_bt*xt.x + a_bb*xb.x;
        ot.y = xt.y;                    ob.y = xb.y;
        ot.z = a_tt*xt.z + a_tb*xb.z;   ob.z = a_bt*xt.z + a_bb*xb.z;
        ot.w = xt.w;                    ob.w = xb.w;
    }
    __stcs((float4*)(out + base), ot);
    __stcs((float4*)(out + base + 32*Wn), ob);
}

// ---------------------------------------------------------------------------
extern "C" void kernel_launch(void* const* d_in, const int* in_sizes, int n_in,
                              void* d_out, int out_size) {
    const float* x      = (const float*)d_in[0];
    const float* logdet = (const float*)d_in[1];
    const float* Wq1    = (const float*)d_in[2];
    const float* Wq2    = (const float*)d_in[3];
    const float* Wq3    = (const float*)d_in[4];
    const float* Wk1    = (const float*)d_in[5];
    const float* Wk2    = (const float*)d_in[6];
    const float* Wk3    = (const float*)d_in[7];
    const float* off1   = (const float*)d_in[8];
    const float* off2   = (const float*)d_in[9];
    const float* off3   = (const float*)d_in[10];
    float* out = (float*)d_out;

    prep_kernel<<<288, 256>>>(Wq1, Wq2, Wq3, Wk1, Wk2, Wk3);
    score_kernel<<<2048, 256>>>(x);
    out_kernel<<<12288, 256>>>(x, logdet, off1, off2, off3, out, out_size);
}

// round 6
// speedup vs baseline: 1.5614x; 1.3384x over previous
#include <cuda_runtime.h>
#include <math.h>

#define Bn 128
#define Cn 48
#define Hn 64
#define Wn 64
#define Pn 32
#define OUT_ELEMS (Bn*Cn*Hn*Wn)

// Scratch (no allocations allowed)
__device__ unsigned long long g_M2[Cn*Cn];   // M duplicated (m,m) as f32x2
__device__ float4 g_Spart[1024];             // partials: idx = (b*2+g)*4 + kq
__device__ float  g_A[Bn*2*4];               // attn coeffs per (b,g)
__device__ float  g_ld[Bn];                  // logdet out staging

#define FMA2(acc, mm, vv) asm("fma.rn.f32x2 %0, %1, %2, %0;" : "+l"(acc) : "l"(mm), "l"(vv))
#define PACK2(dst, lo, hi) asm("mov.b64 %0, {%1,%2};" : "=l"(dst) : "f"(lo), "f"(hi))
#define UNPACK2(lo, hi, src) asm("mov.b64 {%0,%1}, %2;" : "=f"(lo), "=f"(hi) : "l"(src))

// ---------------------------------------------------------------------------
// Kernel A: warp-per-output. M[c][c2] = sum_o (Wq1[o,c]Wk1[o,c2]+...)/scale.
// ---------------------------------------------------------------------------
__global__ __launch_bounds__(256) void prep_kernel(
        const float* __restrict__ Wq1, const float* __restrict__ Wq2,
        const float* __restrict__ Wq3, const float* __restrict__ Wk1,
        const float* __restrict__ Wk2, const float* __restrict__ Wk3) {
    int w    = (blockIdx.x * 256 + threadIdx.x) >> 5;
    int lane = threadIdx.x & 31;
    if (w >= Cn*Cn) return;
    int c = w / Cn, c2 = w % Cn;

    float s = 0.f;
    #pragma unroll
    for (int o = lane; o < Cn; o += 32) {
        s += Wq1[o*Cn+c]*Wk1[o*Cn+c2]
           + Wq2[o*Cn+c]*Wk2[o*Cn+c2]
           + Wq3[o*Cn+c]*Wk3[o*Cn+c2];
    }
    #pragma unroll
    for (int off = 16; off; off >>= 1)
        s += __shfl_xor_sync(0xffffffffu, s, off);

    if (lane == 0) {
        s *= (1.0f / sqrtf((float)(Cn*Pn*Pn)));
        ((float2*)g_M2)[w] = make_float2(s, s);
    }
}

// ---------------------------------------------------------------------------
// Kernel B: scores. Grid 1024: bid -> (b, g, k-quarter kq). Block 256 = 8 warps.
// Stage V[48][128] packed (vt,vb) pairs (8 y-rows x 16 cols, parity g).
// Warp ci owns M-rows ci*6..+5; lane owns k = kl + {0,32,64,96}.
// Per k-step: 4 strided LDS.64 + 6 broadcast LDS.64 -> 24 independent FMA2.
// ---------------------------------------------------------------------------
__global__ __launch_bounds__(256, 3) void score_kernel(const float* __restrict__ x) {
    __shared__ unsigned long long sV[Cn*128];   // 49152 B  [c][k]
    __shared__ unsigned long long sM2[Cn*Cn];   // 18432 B
    __shared__ float4 sred[8];

    const int bid = blockIdx.x;
    const int kq = bid & 3;            // k-quarter (8 y-rows)
    const int g  = (bid >> 2) & 1;     // column-parity group
    const int b  = bid >> 3;
    const int tid = threadIdx.x;

    for (int i = tid; i < Cn*Cn; i += 256) sM2[i] = g_M2[i];

    const float2* xb2 = (const float2*)(x + (size_t)b * Cn * Hn * Wn);

    // stage V: 6144 entries / 256 threads = 24 iters, coalesced float2 loads
    for (int idx = tid; idx < Cn*128; idx += 256) {
        int c2 = idx >> 7;
        int k  = idx & 127;
        int yy = k >> 4;
        int xx = k & 15;
        int yt = kq*8 + yy;
        float2 a  = xb2[((size_t)c2*Hn + yt)*32      + g*16 + xx];
        float2 bb = xb2[((size_t)c2*Hn + yt + 32)*32 + g*16 + xx];
        unsigned long long pk;
        if (g == 0) PACK2(pk, a.x, bb.x);
        else        PACK2(pk, a.y, bb.y);
        sV[idx] = pk;
    }
    __syncthreads();

    const int ci = tid >> 5;           // warp id: M-row group
    const int kl = tid & 31;           // k lane

    unsigned long long acc[24];
    #pragma unroll
    for (int i = 0; i < 24; ++i) acc[i] = 0ULL;

    #pragma unroll
    for (int c2 = 0; c2 < Cn; ++c2) {
        unsigned long long v0 = sV[c2*128 + kl];
        unsigned long long v1 = sV[c2*128 + kl + 32];
        unsigned long long v2 = sV[c2*128 + kl + 64];
        unsigned long long v3 = sV[c2*128 + kl + 96];
        #pragma unroll
        for (int r = 0; r < 6; ++r) {
            unsigned long long m = sM2[(ci*6 + r)*Cn + c2];   // broadcast
            FMA2(acc[r*4    ], m, v0);
            FMA2(acc[r*4 + 1], m, v1);
            FMA2(acc[r*4 + 2], m, v2);
            FMA2(acc[r*4 + 3], m, v3);
        }
    }

    // epilogue: p = v . w dots
    float p00 = 0.f, p01 = 0.f, p10 = 0.f, p11 = 0.f;
    #pragma unroll
    for (int r = 0; r < 6; ++r) {
        #pragma unroll
        for (int j = 0; j < 4; ++j) {
            float wt, wb, vt, vb;
            UNPACK2(wt, wb, acc[r*4 + j]);
            unsigned long long v = sV[(ci*6 + r)*128 + kl + j*32];
            UNPACK2(vt, vb, v);
            p00 = fmaf(vt, wt, p00);  p01 = fmaf(vt, wb, p01);
            p10 = fmaf(vb, wt, p10);  p11 = fmaf(vb, wb, p11);
        }
    }

    #pragma unroll
    for (int off = 16; off; off >>= 1) {
        p00 += __shfl_xor_sync(0xffffffffu, p00, off);
        p01 += __shfl_xor_sync(0xffffffffu, p01, off);
        p10 += __shfl_xor_sync(0xffffffffu, p10, off);
        p11 += __shfl_xor_sync(0xffffffffu, p11, off);
    }
    if (kl == 0) sred[ci] = make_float4(p00, p01, p10, p11);
    __syncthreads();
    if (tid == 0) {
        float4 sv = sred[0];
        #pragma unroll
        for (int w = 1; w < 8; ++w) {
            float4 t = sred[w];
            sv.x += t.x; sv.y += t.y; sv.z += t.z; sv.w += t.w;
        }
        g_Spart[(b*2+g)*4 + kq] = sv;
    }
}

// ---------------------------------------------------------------------------
// Kernel C: softmax coeffs + logdet (R1-style separate tiny kernel).
// ---------------------------------------------------------------------------
__global__ void attn_kernel(const float* __restrict__ logdet_in,
                            const float* __restrict__ off1p,
                            const float* __restrict__ off2p,
                            const float* __restrict__ off3p,
                            float* __restrict__ out, int out_size) {
    int b = threadIdx.x;
    if (b >= Bn) return;
    const float off  = off1p[0];
    const float off2 = off2p[0];
    const float off3 = off3p[0];
    float ld = logdet_in[b];

    #pragma unroll
    for (int g = 0; g < 2; ++g) {
        float4 s = g_Spart[(b*2+g)*4 + 0];
        #pragma unroll
        for (int qq = 1; qq < 4; ++qq) {
            float4 t = g_Spart[(b*2+g)*4 + qq];
            s.x += t.x; s.y += t.y; s.z += t.z; s.w += t.w;
        }
        float stt = s.x + off3, stb = s.y + off3;
        float sbt = s.z + off3, sbb = s.w + off3;
        float z = off3;

        float mx   = fmaxf(fmaxf(stt, stb), z);
        float e0   = expf(stt-mx), e1 = expf(stb-mx), ez = expf(z-mx);
        float inv  = 1.f / (e0 + e1 + 2.f*ez);
        float a_tt = e0*inv + off2 + off;
        float a_tb = e1*inv + off2;

        mx  = fmaxf(fmaxf(sbt, sbb), z);
        e0  = expf(sbt-mx); e1 = expf(sbb-mx); ez = expf(z-mx);
        inv = 1.f / (e0 + e1 + 2.f*ez);
        float a_bt = e0*inv + off2;
        float a_bb = e1*inv + off2 + off;

        float det = a_tt*a_bb - a_tb*a_bt;
        ld += logf(fabsf(det)) * (float)(Pn*(Pn/2)*Cn);

        float* a = &g_A[(b*2+g)*4];
        a[0]=a_tt; a[1]=a_tb; a[2]=a_bt; a[3]=a_bb;
    }
    if (OUT_ELEMS + b < out_size) out[OUT_ELEMS + b] = ld;
}

// ---------------------------------------------------------------------------
// Kernel D: output assembly (exact R1 structure — measured 27.2us).
// ---------------------------------------------------------------------------
__global__ __launch_bounds__(256) void out_kernel(const float* __restrict__ x,
                                                  float* __restrict__ out) {
    int t  = blockIdx.x * blockDim.x + threadIdx.x;
    int x4 = t & 15;
    int y  = (t >> 4) & 31;
    int r  = t >> 9;
    int c  = r % Cn;
    int b  = r / Cn;
    int g  = x4 >> 3;

    const float* A = &g_A[(b*2+g)*4];
    float a_tt = __ldg(&A[0]), a_tb = __ldg(&A[1]);
    float a_bt = __ldg(&A[2]), a_bb = __ldg(&A[3]);

    size_t base = (((size_t)b*Cn + c)*Hn + y)*Wn + x4*4;
    float4 xt = *(const float4*)(x + base);
    float4 xb = *(const float4*)(x + base + 32*Wn);
    float4 ot, ob;
    if (g == 0) {  // pass-through at even lane (x,z)
        ot.x = xt.x;                    ob.x = xb.x;
        ot.y = a_tt*xt.y + a_tb*xb.y;   ob.y = a_bt*xt.y + a_bb*xb.y;
        ot.z = xt.z;                    ob.z = xb.z;
        ot.w = a_tt*xt.w + a_tb*xb.w;   ob.w = a_bt*xt.w + a_bb*xb.w;
    } else {       // pass-through at odd lane (y,w)
        ot.x = a_tt*xt.x + a_tb*xb.x;   ob.x = a_bt*xt.x + a_bb*xb.x;
        ot.y = xt.y;                    ob.y = xb.y;
        ot.z = a_tt*xt.z + a_tb*xb.z;   ob.z = a_bt*xt.z + a_bb*xb.z;
        ot.w = xt.w;                    ob.w = xb.w;
    }
    *(float4*)(out + base)          = ot;
    *(float4*)(out + base + 32*Wn)  = ob;
}

// ---------------------------------------------------------------------------
extern "C" void kernel_launch(void* const* d_in, const int* in_sizes, int n_in,
                              void* d_out, int out_size) {
    const float* x      = (const float*)d_in[0];
    const float* logdet = (const float*)d_in[1];
    const float* Wq1    = (const float*)d_in[2];
    const float* Wq2    = (const float*)d_in[3];
    const float* Wq3    = (const float*)d_in[4];
    const float* Wk1    = (const float*)d_in[5];
    const float* Wk2    = (const float*)d_in[6];
    const float* Wk3    = (const float*)d_in[7];
    const float* off1   = (const float*)d_in[8];
    const float* off2   = (const float*)d_in[9];
    const float* off3   = (const float*)d_in[10];
    float* out = (float*)d_out;

    prep_kernel<<<288, 256>>>(Wq1, Wq2, Wq3, Wk1, Wk2, Wk3);
    score_kernel<<<1024, 256>>>(x);
    attn_kernel<<<1, 128>>>(logdet, off1, off2, off3, out, out_size);
    out_kernel<<<12288, 256>>>(x, out);
}